// round 4
// baseline (speedup 1.0000x reference)
#include <cuda_runtime.h>
#include <cuda_bf16.h>
#include <math.h>

#define BB    64
#define NN    4096
#define DD    256
#define KK    11
#define HH    512
#define NITER 5
#define EPSF     1e-8f
#define LN_EPSF  1e-5f
#define SCALEF   0.0625f
#define SPLITN   16
#define TOKB   (NN/SPLITN)   /* 256 tokens per block */
#define TOKW   (TOKB/4)      /* 64 tokens per warp (4 warps/block) */
#define SLOTSZ (BB*KK*DD)

// ------------------------- static device scratch -------------------------
__device__ __align__(16) float g_xh  [(size_t)BB*NN*DD];   // pre-affine LN(inputs), fp32
__device__ __align__(16) float g_Mqk [DD*DD];              // [e][f]
__device__ __align__(16) float g_MqkT[DD*DD];              // [f][e]
__device__ __align__(16) float g_slots[SLOTSZ];
__device__ __align__(16) float g_qt   [SLOTSZ];            // (LN_s(slots)@Mqk) ⊙ ln_f_w
__device__ __align__(16) float g_qbias[BB*KK];
__device__ __align__(16) float g_pU [(size_t)BB*SPLITN*KK*DD];
__device__ __align__(16) float g_pS [BB*SPLITN*16];

// ------------------------- f32x2 helpers -------------------------
typedef unsigned long long ull;
__device__ __forceinline__ ull pk2(float lo, float hi) {
    ull r; asm("mov.b64 %0, {%1, %2};" : "=l"(r) : "f"(lo), "f"(hi)); return r;
}
__device__ __forceinline__ void upk2(float& lo, float& hi, ull v) {
    asm("mov.b64 {%0, %1}, %2;" : "=f"(lo), "=f"(hi) : "l"(v));
}
__device__ __forceinline__ ull fma2(ull a, ull b, ull c) {
    ull d; asm("fma.rn.f32x2 %0, %1, %2, %3;" : "=l"(d) : "l"(a), "l"(b), "l"(c)); return d;
}
__device__ __forceinline__ ull mul2(ull a, ull b) {
    ull d; asm("mul.rn.f32x2 %0, %1, %2;" : "=l"(d) : "l"(a), "l"(b)); return d;
}
__device__ __forceinline__ float collapse2(ull v) {
    float lo, hi; upk2(lo, hi, v); return lo + hi;
}

__device__ __forceinline__ float blockSum256(float v, float* red) {
    // requires blockDim.x == 256
    #pragma unroll
    for (int o = 16; o; o >>= 1) v += __shfl_xor_sync(0xffffffffu, v, o);
    int lane = threadIdx.x & 31, wid = threadIdx.x >> 5;
    __syncthreads();
    if (lane == 0) red[wid] = v;
    __syncthreads();
    float t = 0.f;
    #pragma unroll
    for (int w = 0; w < 8; w++) t += red[w];
    return t;
}

__device__ __forceinline__ float sigm(float x) { return 1.f / (1.f + __expf(-x)); }

// ------------------------- prep: x_hat = (x - m) * rsqrt(var + eps), pre-affine -------------------------
__global__ void k_xhat(const float* __restrict__ inp) {
    // warp per token; block = 8 tokens
    int l = threadIdx.x & 31, w = threadIdx.x >> 5;
    size_t row = (size_t)blockIdx.x * 8 + w;
    const float4* rp = (const float4*)(inp + row * DD);
    float4 a = rp[2 * l], b = rp[2 * l + 1];
    float s = a.x + a.y + a.z + a.w + b.x + b.y + b.z + b.w;
    #pragma unroll
    for (int o = 16; o; o >>= 1) s += __shfl_xor_sync(0xffffffffu, s, o);
    float m = s * (1.f / DD);
    a.x -= m; a.y -= m; a.z -= m; a.w -= m;
    b.x -= m; b.y -= m; b.z -= m; b.w -= m;
    float vs = a.x*a.x + a.y*a.y + a.z*a.z + a.w*a.w
             + b.x*b.x + b.y*b.y + b.z*b.z + b.w*b.w;
    #pragma unroll
    for (int o = 16; o; o >>= 1) vs += __shfl_xor_sync(0xffffffffu, vs, o);
    float rs = rsqrtf(vs * (1.f / DD) + LN_EPSF);
    a.x *= rs; a.y *= rs; a.z *= rs; a.w *= rs;
    b.x *= rs; b.y *= rs; b.z *= rs; b.w *= rs;
    float4* op = (float4*)(g_xh + row * DD);
    op[2 * l] = a; op[2 * l + 1] = b;
}

// ------------------------- prep: Mqk (both layouts) -------------------------
// Mqk[e][f] = sum_d Wq[d][e]*Wk[d][f] * SCALE
__global__ void k_mqk(const float* __restrict__ Wq, const float* __restrict__ Wk) {
    int f = blockIdx.x, e = threadIdx.x;
    float acc = 0.f;
    for (int d = 0; d < DD; d++)
        acc = fmaf(Wq[d * DD + e], Wk[d * DD + f], acc);
    acc *= SCALEF;
    g_MqkT[f * DD + e] = acc;
    g_Mqk [e * DD + f] = acc;
}

// ------------------------- initial qgen (also copies slots) -------------------------
__global__ void k_qgen0(const float* __restrict__ slots_src,
                        const float* __restrict__ lsw, const float* __restrict__ lsb,
                        const float* __restrict__ lfw, const float* __restrict__ lfb) {
    __shared__ float sQ[KK][DD];
    __shared__ float red[32];
    int b = blockIdx.x, t = threadIdx.x;
    for (int r = 0; r < KK; r++) {
        float v = slots_src[(b * KK + r) * DD + t];
        g_slots[(b * KK + r) * DD + t] = v;
        float m = blockSum256(v, red) * (1.f / DD);
        float d = v - m;
        float var = blockSum256(d * d, red) * (1.f / DD);
        sQ[r][t] = d * rsqrtf(var + LN_EPSF) * lsw[t] + lsb[t];
    }
    __syncthreads();
    float acc[KK];
    #pragma unroll
    for (int r = 0; r < KK; r++) acc[r] = 0.f;
    for (int e = 0; e < DD; e++) {
        float mv = g_Mqk[e * DD + t];
        #pragma unroll
        for (int r = 0; r < KK; r++) acc[r] = fmaf(sQ[r][e], mv, acc[r]);
    }
    float wt = lfw[t], bt = lfb[t];
    for (int r = 0; r < KK; r++) {
        float qb = blockSum256(acc[r] * bt, red);
        if (t == 0) g_qbias[b * KK + r] = qb;
    }
    #pragma unroll
    for (int r = 0; r < KK; r++) g_qt[(b * KK + r) * DD + t] = acc[r] * wt;
}

// ------------------------- per-iter: streaming attention (f32x2) -------------------------
__global__ void __launch_bounds__(128) k_attn() {
    __shared__ float sC[2][KK * DD];      // 22528 B
    __shared__ float sS4[4][16];
    int b = blockIdx.x, sp = blockIdx.y;
    int tid = threadIdx.x, w = tid >> 5, l = tid & 31;

    // q (ln_f_w pre-folded); lane owns dims [8l, 8l+8) as 4 f32x2 pairs
    ull q2[KK][4];
    {
        const float4* qp = (const float4*)(g_qt + (size_t)b * KK * DD);
        #pragma unroll
        for (int i = 0; i < KK; i++) {
            float4 a = qp[i * 64 + 2 * l], c = qp[i * 64 + 2 * l + 1];
            q2[i][0] = pk2(a.x, a.y); q2[i][1] = pk2(a.z, a.w);
            q2[i][2] = pk2(c.x, c.y); q2[i][3] = pk2(c.z, c.w);
        }
    }
    float qb_[KK];
    #pragma unroll
    for (int i = 0; i < KK; i++) qb_[i] = g_qbias[b * KK + i];

    ull U2[KK][4];
    float Sacc[KK];
    #pragma unroll
    for (int i = 0; i < KK; i++) {
        Sacc[i] = 0.f;
        #pragma unroll
        for (int k = 0; k < 4; k++) U2[i][k] = 0ull;
    }

    int j0 = sp * TOKB + w * TOKW;
    const float4* xrow = (const float4*)(g_xh + ((size_t)b * NN + j0) * DD);

    float4 xa = xrow[2 * l], xb = xrow[2 * l + 1];
    for (int tt = 0; tt < TOKW; tt++) {
        int nt = (tt + 1 < TOKW) ? tt + 1 : tt;
        float4 na = xrow[nt * 64 + 2 * l];
        float4 nb = xrow[nt * 64 + 2 * l + 1];

        ull n2[4];
        n2[0] = pk2(xa.x, xa.y); n2[1] = pk2(xa.z, xa.w);
        n2[2] = pk2(xb.x, xb.y); n2[3] = pk2(xb.z, xb.w);

        // dots (f32x2 chains) + pair-collapse
        float p[KK];
        #pragma unroll
        for (int i = 0; i < KK; i++) {
            ull t2 = mul2(q2[i][3], n2[3]);
            t2 = fma2(q2[i][2], n2[2], t2);
            t2 = fma2(q2[i][1], n2[1], t2);
            t2 = fma2(q2[i][0], n2[0], t2);
            p[i] = collapse2(t2);
        }
        #pragma unroll
        for (int o = 16; o; o >>= 1) {
            #pragma unroll
            for (int i = 0; i < KK; i++) p[i] += __shfl_xor_sync(0xffffffffu, p[i], o);
        }
        // softmax over slots (+ EPS)
        float mx = p[0] + qb_[0];
        #pragma unroll
        for (int i = 0; i < KK; i++) { p[i] += qb_[i]; mx = fmaxf(mx, p[i]); }
        float se = 0.f;
        #pragma unroll
        for (int i = 0; i < KK; i++) { p[i] = __expf(p[i] - mx); se += p[i]; }
        float inv = 1.f / se;
        #pragma unroll
        for (int i = 0; i < KK; i++) {
            float a = fmaf(p[i], inv, EPSF);
            Sacc[i] += a;
            ull a2 = pk2(a, a);
            U2[i][0] = fma2(a2, n2[0], U2[i][0]);
            U2[i][1] = fma2(a2, n2[1], U2[i][1]);
            U2[i][2] = fma2(a2, n2[2], U2[i][2]);
            U2[i][3] = fma2(a2, n2[3], U2[i][3]);
        }
        xa = na; xb = nb;
    }

    // block combine (4 warps, 2 smem copies, no atomics)
    float* myc = sC[w & 1];
    if (w < 2) {
        #pragma unroll
        for (int i = 0; i < KK; i++) {
            float u0,u1,u2,u3,u4,u5,u6,u7;
            upk2(u0,u1,U2[i][0]); upk2(u2,u3,U2[i][1]);
            upk2(u4,u5,U2[i][2]); upk2(u6,u7,U2[i][3]);
            *(float4*)&myc[i * DD + 8 * l]     = make_float4(u0,u1,u2,u3);
            *(float4*)&myc[i * DD + 8 * l + 4] = make_float4(u4,u5,u6,u7);
        }
    }
    __syncthreads();
    if (w >= 2) {
        #pragma unroll
        for (int i = 0; i < KK; i++) {
            float u0,u1,u2,u3,u4,u5,u6,u7;
            upk2(u0,u1,U2[i][0]); upk2(u2,u3,U2[i][1]);
            upk2(u4,u5,U2[i][2]); upk2(u6,u7,U2[i][3]);
            float4 a = *(float4*)&myc[i * DD + 8 * l];
            float4 c = *(float4*)&myc[i * DD + 8 * l + 4];
            a.x += u0; a.y += u1; a.z += u2; a.w += u3;
            c.x += u4; c.y += u5; c.z += u6; c.w += u7;
            *(float4*)&myc[i * DD + 8 * l]     = a;
            *(float4*)&myc[i * DD + 8 * l + 4] = c;
        }
    }
    if (l == 0) {
        #pragma unroll
        for (int i = 0; i < KK; i++) sS4[w][i] = Sacc[i];
    }
    __syncthreads();
    float* outp = g_pU + ((size_t)(b * SPLITN + sp)) * (KK * DD);
    for (int idx = tid; idx < KK * DD; idx += 128)
        outp[idx] = sC[0][idx] + sC[1][idx];
    if (tid < KK)
        g_pS[(b * SPLITN + sp) * 16 + tid] =
            sS4[0][tid] + sS4[1][tid] + sS4[2][tid] + sS4[3][tid];
}

// ------------------------- per-iter: fused update -------------------------
// grid = 64 (one block per batch), 768 threads, 79KB dynamic smem.
// Stages: combine partials -> Wv -> GRU -> LN_p -> MLP -> residual -> qgen(next)
#define SM_B0 0
#define SM_B1 2816
#define SM_B2 5632      /* size 8448 */
#define SM_B3 14080
#define SM_B4 16896
#define SM_SS 19712     /* 16 */
#define SM_ST 19728     /* 32: mean[0..10], rstd[16..26] */
#define SM_QB 19760     /* 16 */
#define SM_TOTF 19776

__global__ void __launch_bounds__(768) k_update(
    const float* __restrict__ lfw, const float* __restrict__ lfb,
    const float* __restrict__ lpw, const float* __restrict__ lpb,
    const float* __restrict__ lsw, const float* __restrict__ lsb,
    const float* __restrict__ Wv,
    const float* __restrict__ Wih, const float* __restrict__ bih,
    const float* __restrict__ Whh, const float* __restrict__ bhh,
    const float* __restrict__ W1,  const float* __restrict__ b1,
    const float* __restrict__ W2,  const float* __restrict__ b2,
    float* __restrict__ outp)
{
    extern __shared__ float dsm[];
    float* buf0 = dsm + SM_B0;   // un / LN_p out / LN_s out
    float* buf1 = dsm + SM_B1;   // prev slots -> hy
    float* buf2 = dsm + SM_B2;   // gates [r][768] -> h1 [r][512]
    float* buf3 = dsm + SM_B3;   // hn
    float* buf4 = dsm + SM_B4;   // updates -> final slots
    float* sS   = dsm + SM_SS;
    float* stat = dsm + SM_ST;
    float* sQB  = dsm + SM_QB;

    int b = blockIdx.x, tid = threadIdx.x;
    int w = tid >> 5, l = tid & 31;

    // ---- Stage A: combine attention partials; load prev slots ----
    if (tid < 16) sQB[tid] = 0.f;
    if (tid < KK) {
        float s = 0.f;
        #pragma unroll
        for (int sp = 0; sp < SPLITN; sp++) s += g_pS[(b * SPLITN + sp) * 16 + tid];
        sS[tid] = s;
    }
    for (int idx = tid; idx < KK * DD; idx += 768) {
        float u = 0.f;
        #pragma unroll
        for (int sp = 0; sp < SPLITN; sp++)
            u += g_pU[((size_t)(b * SPLITN + sp)) * (KK * DD) + idx];
        buf0[idx] = u;
        buf1[idx] = g_slots[b * (KK * DD) + idx];
    }
    __syncthreads();
    for (int idx = tid; idx < KK * DD; idx += 768) {
        int r = idx >> 8, d = idx & 255;
        buf0[idx] = fmaf(lfw[d], buf0[idx] / sS[r], lfb[d]);
    }
    __syncthreads();

    // ---- Stage B: updates[r][d] = sum_e un[r][e] * Wv[d][e] ----
    {
        int d = tid & 255, rg = tid >> 8;
        int nr = (rg == 2) ? 3 : 4;
        ull a2[4] = {0ull, 0ull, 0ull, 0ull};
        const ulonglong2* wv = (const ulonglong2*)(Wv + d * DD);
        for (int e4 = 0; e4 < DD / 4; e4++) {
            ulonglong2 ww = wv[e4];
            #pragma unroll 4
            for (int k = 0; k < nr; k++) {
                int r = rg + 3 * k;
                ulonglong2 uu = *(const ulonglong2*)&buf0[r * DD + e4 * 4];
                a2[k] = fma2(uu.x, ww.x, a2[k]);
                a2[k] = fma2(uu.y, ww.y, a2[k]);
            }
        }
        // write after compute; buf4 not yet used this launch
        for (int k = 0; k < nr; k++)
            buf4[(rg + 3 * k) * DD + d] = collapse2(a2[k]);
    }
    __syncthreads();

    // ---- Stage C: GRU gates. thread j streams Wih/Whh row j ----
    {
        int j = tid;  // 0..767
        ull gi2[KK], gh2[KK];
        #pragma unroll
        for (int r = 0; r < KK; r++) { gi2[r] = 0ull; gh2[r] = 0ull; }
        const ulonglong2* wi = (const ulonglong2*)(Wih + j * DD);
        const ulonglong2* wh = (const ulonglong2*)(Whh + j * DD);
        for (int e4 = 0; e4 < DD / 4; e4++) {
            ulonglong2 a = wi[e4], c = wh[e4];
            #pragma unroll
            for (int r = 0; r < KK; r++) {
                ulonglong2 uu = *(const ulonglong2*)&buf4[r * DD + e4 * 4];
                ulonglong2 hh = *(const ulonglong2*)&buf1[r * DD + e4 * 4];
                gi2[r] = fma2(uu.x, a.x, gi2[r]);
                gi2[r] = fma2(uu.y, a.y, gi2[r]);
                gh2[r] = fma2(hh.x, c.x, gh2[r]);
                gh2[r] = fma2(hh.y, c.y, gh2[r]);
            }
        }
        float bi = bih[j], bh = bhh[j];
        if (j < 2 * DD) {
            #pragma unroll
            for (int r = 0; r < KK; r++)
                buf2[r * 768 + j] = (collapse2(gi2[r]) + bi) + (collapse2(gh2[r]) + bh);
        } else {
            #pragma unroll
            for (int r = 0; r < KK; r++) {
                buf2[r * 768 + j] = collapse2(gi2[r]) + bi;       // i_n
                buf3[r * DD + (j - 2 * DD)] = collapse2(gh2[r]) + bh; // h_n
            }
        }
    }
    __syncthreads();

    // ---- Stage D: GRU nonlinearity + LN_p ----
    if (tid < DD) {
        int d = tid;
        #pragma unroll
        for (int r = 0; r < KK; r++) {
            float rg = sigm(buf2[r * 768 + d]);
            float zz = sigm(buf2[r * 768 + DD + d]);
            float nn = tanhf(fmaf(rg, buf3[r * DD + d], buf2[r * 768 + 2 * DD + d]));
            float hp = buf1[r * DD + d];
            buf1[r * DD + d] = fmaf(zz, hp - nn, nn);   // new hy
        }
    }
    __syncthreads();
    if (w < KK) {  // warp w computes LN stats for slot r=w over buf1
        float4 a = *(float4*)&buf1[w * DD + l * 8];
        float4 c = *(float4*)&buf1[w * DD + l * 8 + 4];
        float s = a.x + a.y + a.z + a.w + c.x + c.y + c.z + c.w;
        float q = a.x*a.x + a.y*a.y + a.z*a.z + a.w*a.w
                + c.x*c.x + c.y*c.y + c.z*c.z + c.w*c.w;
        #pragma unroll
        for (int o = 16; o; o >>= 1) {
            s += __shfl_xor_sync(0xffffffffu, s, o);
            q += __shfl_xor_sync(0xffffffffu, q, o);
        }
        if (l == 0) {
            float m = s * (1.f / DD);
            float var = fmaxf(q * (1.f / DD) - m * m, 0.f);
            stat[w] = m;
            stat[16 + w] = rsqrtf(var + LN_EPSF);
        }
    }
    __syncthreads();
    for (int idx = tid; idx < KK * DD; idx += 768) {
        int r = idx >> 8, d = idx & 255;
        buf0[idx] = fmaf((buf1[idx] - stat[r]) * stat[16 + r], lpw[d], lpb[d]);
    }
    __syncthreads();

    // ---- Stage E: MLP1: h1[r][h] = relu(sum_e p[r][e]*W1[h][e] + b1[h]) ----
    if (tid < HH) {
        int h = tid;
        ull a2[KK];
        #pragma unroll
        for (int r = 0; r < KK; r++) a2[r] = 0ull;
        const ulonglong2* w1 = (const ulonglong2*)(W1 + h * DD);
        for (int e4 = 0; e4 < DD / 4; e4++) {
            ulonglong2 ww = w1[e4];
            #pragma unroll
            for (int r = 0; r < KK; r++) {
                ulonglong2 pp = *(const ulonglong2*)&buf0[r * DD + e4 * 4];
                a2[r] = fma2(pp.x, ww.x, a2[r]);
                a2[r] = fma2(pp.y, ww.y, a2[r]);
            }
        }
        float bb = b1[h];
        #pragma unroll
        for (int r = 0; r < KK; r++)
            buf2[r * HH + h] = fmaxf(collapse2(a2[r]) + bb, 0.f);
    }
    __syncthreads();

    // ---- Stage F: MLP2 + residual; write slots & output ----
    {
        int d = tid & 255, rg = tid >> 8;
        int nr = (rg == 2) ? 3 : 4;
        ull a2[4] = {0ull, 0ull, 0ull, 0ull};
        const ulonglong2* w2 = (const ulonglong2*)(W2 + d * HH);
        for (int h4 = 0; h4 < HH / 4; h4++) {
            ulonglong2 ww = w2[h4];
            #pragma unroll 4
            for (int k = 0; k < nr; k++) {
                int r = rg + 3 * k;
                ulonglong2 hh = *(const ulonglong2*)&buf2[r * HH + h4 * 4];
                a2[k] = fma2(hh.x, ww.x, a2[k]);
                a2[k] = fma2(hh.y, ww.y, a2[k]);
            }
        }
        float bb = b2[d];
        for (int k = 0; k < nr; k++) {
            int r = rg + 3 * k;
            float fin = collapse2(a2[k]) + bb + buf1[r * DD + d];
            g_slots[(b * KK + r) * DD + d] = fin;
            outp[(b * KK + r) * DD + d] = fin;
            buf4[r * DD + d] = fin;
        }
    }
    __syncthreads();

    // ---- Stage G: qgen for next iteration ----
    if (w < KK) {  // LN_s stats on buf4
        float4 a = *(float4*)&buf4[w * DD + l * 8];
        float4 c = *(float4*)&buf4[w * DD + l * 8 + 4];
        float s = a.x + a.y + a.z + a.w + c.x + c.y + c.z + c.w;
        float q = a.x*a.x + a.y*a.y + a.z*a.z + a.w*a.w
                + c.x*c.x + c.y*c.y + c.z*c.z + c.w*c.w;
        #pragma unroll
        for (int o = 16; o; o >>= 1) {
            s += __shfl_xor_sync(0xffffffffu, s, o);
            q += __shfl_xor_sync(0xffffffffu, q, o);
        }
        if (l == 0) {
            float m = s * (1.f / DD);
            float var = fmaxf(q * (1.f / DD) - m * m, 0.f);
            stat[w] = m;
            stat[16 + w] = rsqrtf(var + LN_EPSF);
        }
    }
    __syncthreads();
    for (int idx = tid; idx < KK * DD; idx += 768) {
        int r = idx >> 8, d = idx & 255;
        buf0[idx] = fmaf((buf4[idx] - stat[r]) * stat[16 + r], lsw[d], lsb[d]);
    }
    __syncthreads();
    {
        int f = tid & 255, rg = tid >> 8;
        int nr = (rg == 2) ? 3 : 4;
        ull a2[4] = {0ull, 0ull, 0ull, 0ull};
        const ulonglong2* mk = (const ulonglong2*)(g_MqkT + f * DD);
        for (int e4 = 0; e4 < DD / 4; e4++) {
            ulonglong2 ww = mk[e4];
            #pragma unroll 4
            for (int k = 0; k < nr; k++) {
                int r = rg + 3 * k;
                ulonglong2 qq = *(const ulonglong2*)&buf0[r * DD + e4 * 4];
                a2[k] = fma2(qq.x, ww.x, a2[k]);
                a2[k] = fma2(qq.y, ww.y, a2[k]);
            }
        }
        float wt = lfw[f], bt = lfb[f];
        for (int k = 0; k < nr; k++) {
            int r = rg + 3 * k;
            float qpre = collapse2(a2[k]);
            g_qt[(b * KK + r) * DD + f] = qpre * wt;
            float part = qpre * bt;
            #pragma unroll
            for (int o = 16; o; o >>= 1) part += __shfl_xor_sync(0xffffffffu, part, o);
            if (l == 0) atomicAdd(&sQB[r], part);
        }
    }
    __syncthreads();
    if (tid < KK) g_qbias[b * KK + tid] = sQB[tid];
}

// ------------------------- launch -------------------------
extern "C" void kernel_launch(void* const* d_in, const int* in_sizes, int n_in,
                              void* d_out, int out_size) {
    const float* inputs = (const float*)d_in[0];
    const float* slots0 = (const float*)d_in[1];
    const float* ln_f_w = (const float*)d_in[2];
    const float* ln_f_b = (const float*)d_in[3];
    const float* ln_s_w = (const float*)d_in[4];
    const float* ln_s_b = (const float*)d_in[5];
    const float* ln_p_w = (const float*)d_in[6];
    const float* ln_p_b = (const float*)d_in[7];
    const float* Wq  = (const float*)d_in[8];
    const float* Wk  = (const float*)d_in[9];
    const float* Wv  = (const float*)d_in[10];
    const float* Wih = (const float*)d_in[11];
    const float* bih = (const float*)d_in[12];
    const float* Whh = (const float*)d_in[13];
    const float* bhh = (const float*)d_in[14];
    const float* W1  = (const float*)d_in[15];
    const float* b1  = (const float*)d_in[16];
    const float* W2  = (const float*)d_in[17];
    const float* b2  = (const float*)d_in[18];
    float* outp = (float*)d_out;

    static int smem_set = 0;
    if (!smem_set) {
        cudaFuncSetAttribute(k_update, cudaFuncAttributeMaxDynamicSharedMemorySize,
                             SM_TOTF * sizeof(float));
        smem_set = 1;
    }

    // launch order: 0 xhat, 1 mqk, 2 qgen0, 3 attn, 4 update, 5 attn, ...
    k_xhat<<<(BB * NN) / 8, 256>>>(inputs);
    k_mqk<<<DD, DD>>>(Wq, Wk);
    k_qgen0<<<BB, DD>>>(slots0, ln_s_w, ln_s_b, ln_f_w, ln_f_b);

    for (int it = 0; it < NITER; it++) {
        k_attn<<<dim3(BB, SPLITN), 128>>>();
        k_update<<<BB, 768, SM_TOTF * sizeof(float)>>>(
            ln_f_w, ln_f_b, ln_p_w, ln_p_b, ln_s_w, ln_s_b,
            Wv, Wih, bih, Whh, bhh, W1, b1, W2, b2, outp);
    }
}

// round 5
// speedup vs baseline: 1.8794x; 1.8794x over previous
#include <cuda_runtime.h>
#include <cuda_bf16.h>
#include <math.h>

#define BB    64
#define NN    4096
#define DD    256
#define KK    11
#define HH    512
#define NITER 5
#define EPSF     1e-8f
#define LN_EPSF  1e-5f
#define SCALEF   0.0625f
#define SPLITN   16
#define TOKB   (NN/SPLITN)   /* 256 tokens per block */
#define TOKW   (TOKB/4)      /* 64 tokens per warp (4 warps/block) */
#define SLOTSZ (BB*KK*DD)

// ------------------------- static device scratch -------------------------
__device__ __align__(16) float g_xh  [(size_t)BB*NN*DD];   // pre-affine LN(inputs)
__device__ __align__(16) float g_slots[SLOTSZ];
__device__ __align__(16) float g_qt   [SLOTSZ];            // (LN_s@WqT@Wk*SCALE) ⊙ ln_f_w
__device__ __align__(16) float g_qbias[BB*KK];
__device__ __align__(16) float g_pU [(size_t)BB*SPLITN*KK*DD];
__device__ __align__(16) float g_pS [BB*SPLITN*16];
// packed weights: Wp[e4*J + j] = float4(W[j][4e4..4e4+3])
__device__ __align__(16) float g_Wvp [DD*DD];
__device__ __align__(16) float g_Wihp[3*DD*DD];
__device__ __align__(16) float g_Whhp[3*DD*DD];
__device__ __align__(16) float g_W1p [HH*DD];
__device__ __align__(16) float g_W2p [DD*HH];
__device__ __align__(16) float g_Wqp [DD*DD];
__device__ __align__(16) float g_Wkcp[DD*DD];   // Wkcp[d4*256+f] = Wk[4d4+i][f]

// ------------------------- f32x2 helpers -------------------------
typedef unsigned long long ull;
__device__ __forceinline__ ull pk2(float lo, float hi) {
    ull r; asm("mov.b64 %0, {%1, %2};" : "=l"(r) : "f"(lo), "f"(hi)); return r;
}
__device__ __forceinline__ void upk2(float& lo, float& hi, ull v) {
    asm("mov.b64 {%0, %1}, %2;" : "=f"(lo), "=f"(hi) : "l"(v));
}
__device__ __forceinline__ ull fma2(ull a, ull b, ull c) {
    ull d; asm("fma.rn.f32x2 %0, %1, %2, %3;" : "=l"(d) : "l"(a), "l"(b), "l"(c)); return d;
}
__device__ __forceinline__ ull mul2(ull a, ull b) {
    ull d; asm("mul.rn.f32x2 %0, %1, %2;" : "=l"(d) : "l"(a), "l"(b)); return d;
}
__device__ __forceinline__ float collapse2(ull v) {
    float lo, hi; upk2(lo, hi, v); return lo + hi;
}
__device__ __forceinline__ float sigm(float x) { return 1.f / (1.f + __expf(-x)); }

// ------------------------- prep: xhat + weight packing (one launch) -------------------------
#define XHB 32768
__global__ void k_prep(const float* __restrict__ inp,
                       const float* __restrict__ Wq, const float* __restrict__ Wk,
                       const float* __restrict__ Wv,
                       const float* __restrict__ Wih, const float* __restrict__ Whh,
                       const float* __restrict__ W1,  const float* __restrict__ W2) {
    if (blockIdx.x < XHB) {
        // x_hat: warp per token, 8 tokens per block
        int l = threadIdx.x & 31, w = threadIdx.x >> 5;
        size_t row = (size_t)blockIdx.x * 8 + w;
        const float4* rp = (const float4*)(inp + row * DD);
        float4 a = rp[2 * l], b = rp[2 * l + 1];
        float s = a.x + a.y + a.z + a.w + b.x + b.y + b.z + b.w;
        #pragma unroll
        for (int o = 16; o; o >>= 1) s += __shfl_xor_sync(0xffffffffu, s, o);
        float m = s * (1.f / DD);
        a.x -= m; a.y -= m; a.z -= m; a.w -= m;
        b.x -= m; b.y -= m; b.z -= m; b.w -= m;
        float vs = a.x*a.x + a.y*a.y + a.z*a.z + a.w*a.w
                 + b.x*b.x + b.y*b.y + b.z*b.z + b.w*b.w;
        #pragma unroll
        for (int o = 16; o; o >>= 1) vs += __shfl_xor_sync(0xffffffffu, vs, o);
        float rs = rsqrtf(vs * (1.f / DD) + LN_EPSF);
        a.x *= rs; a.y *= rs; a.z *= rs; a.w *= rs;
        b.x *= rs; b.y *= rs; b.z *= rs; b.w *= rs;
        float4* op = (float4*)(g_xh + row * DD);
        op[2 * l] = a; op[2 * l + 1] = b;
        return;
    }
    // ---- weight packing ----
    __shared__ float tile[32][33];
    int bid = blockIdx.x - XHB;
    const float* src; float* dst; int J, E, trans, t0;
    if      (bid < 64)  { src = Wv;  dst = g_Wvp;  J = DD;   E = DD; trans = 0; t0 = 0;   }
    else if (bid < 256) { src = Wih; dst = g_Wihp; J = 3*DD; E = DD; trans = 0; t0 = 64;  }
    else if (bid < 448) { src = Whh; dst = g_Whhp; J = 3*DD; E = DD; trans = 0; t0 = 256; }
    else if (bid < 576) { src = W1;  dst = g_W1p;  J = HH;   E = DD; trans = 0; t0 = 448; }
    else if (bid < 704) { src = W2;  dst = g_W2p;  J = DD;   E = HH; trans = 0; t0 = 576; }
    else if (bid < 768) { src = Wq;  dst = g_Wqp;  J = DD;   E = DD; trans = 0; t0 = 704; }
    else                { src = Wk;  dst = g_Wkcp; J = DD;   E = DD; trans = 1; t0 = 768; }
    int tt = bid - t0;
    int nj = J / 32;
    int tj = tt % nj, te = tt / nj;
    int tx = threadIdx.x & 31, ty = threadIdx.x >> 5;   // 32 x 8

    if (!trans) {
        // read W[j][e] coalesced: tile[j_local][e_local]
        #pragma unroll
        for (int yy = 0; yy < 32; yy += 8) {
            int j = tj * 32 + ty + yy, e = te * 32 + tx;
            tile[ty + yy][tx] = src[(size_t)j * E + e];
        }
        __syncthreads();
        // write dst[e4][j] = float4(W[j][4e4..])  -> tile[tx][4*ty + i]
        int e4 = te * 8 + ty, j = tj * 32 + tx;
        float4 v = make_float4(tile[tx][4*ty+0], tile[tx][4*ty+1],
                               tile[tx][4*ty+2], tile[tx][4*ty+3]);
        ((float4*)dst)[(size_t)e4 * J + j] = v;
    } else {
        // logical W'[f][d] = Wk[d][f]; read Wk coalesced: tile[d_local][f_local]
        #pragma unroll
        for (int yy = 0; yy < 32; yy += 8) {
            int d = te * 32 + ty + yy, f = tj * 32 + tx;
            tile[ty + yy][tx] = src[(size_t)d * J + f];
        }
        __syncthreads();
        int d4 = te * 8 + ty, f = tj * 32 + tx;
        float4 v = make_float4(tile[4*ty+0][tx], tile[4*ty+1][tx],
                               tile[4*ty+2][tx], tile[4*ty+3][tx]);
        ((float4*)dst)[(size_t)d4 * J + f] = v;
    }
}

// ------------------------- shared qgen math (stage G) -------------------------
// buf4: slots values (NR x DD), produces g_qt / g_qbias for slots rbase..rbase+NR-1
// uses buf0 (NR*DD), buf2 (>= NR*DD), stat[32], sQB[16]
__device__ __forceinline__ void qgen_core(
    int b, int rbase, int NR,
    float* buf4, float* buf0, float* buf2, float* stat, float* sQB,
    const float* __restrict__ lsw, const float* __restrict__ lsb,
    const float* __restrict__ lfw, const float* __restrict__ lfb)
{
    int tid = threadIdx.x, w = tid >> 5, l = tid & 31;
    if (tid < 16) sQB[tid] = 0.f;
    // LN_s stats: warp per slot
    if (w < NR) {
        float4 a = *(float4*)&buf4[w * DD + l * 8];
        float4 c = *(float4*)&buf4[w * DD + l * 8 + 4];
        float s = a.x + a.y + a.z + a.w + c.x + c.y + c.z + c.w;
        float q = a.x*a.x + a.y*a.y + a.z*a.z + a.w*a.w
                + c.x*c.x + c.y*c.y + c.z*c.z + c.w*c.w;
        #pragma unroll
        for (int o = 16; o; o >>= 1) {
            s += __shfl_xor_sync(0xffffffffu, s, o);
            q += __shfl_xor_sync(0xffffffffu, q, o);
        }
        if (l == 0) {
            float m = s * (1.f / DD);
            float var = fmaxf(q * (1.f / DD) - m * m, 0.f);
            stat[w] = m;
            stat[16 + w] = rsqrtf(var + LN_EPSF);
        }
    }
    __syncthreads();
    for (int idx = tid; idx < NR * DD; idx += 768) {
        int r = idx >> 8, d = idx & 255;
        buf0[idx] = fmaf((buf4[idx] - stat[r]) * stat[16 + r], lsw[d], lsb[d]);
    }
    __syncthreads();
    // step 1: t[r][d] = sum_e LNs[r][e] * Wq[d][e]
    {
        int d = tid & 255, rg = tid >> 8;
        int r0 = rg, r1 = (rg + 3 < NR) ? rg + 3 : r0;
        ull a0 = 0ull, a1 = 0ull;
        const ulonglong2* wq = (const ulonglong2*)g_Wqp;
        for (int e4 = 0; e4 < DD / 4; e4++) {
            ulonglong2 ww = wq[e4 * DD + d];
            ulonglong2 u0 = *(const ulonglong2*)&buf0[r0 * DD + e4 * 4];
            ulonglong2 u1 = *(const ulonglong2*)&buf0[r1 * DD + e4 * 4];
            a0 = fma2(u0.x, ww.x, a0); a0 = fma2(u0.y, ww.y, a0);
            a1 = fma2(u1.x, ww.x, a1); a1 = fma2(u1.y, ww.y, a1);
        }
        __syncthreads();   // buf2 free
        buf2[r0 * DD + d] = collapse2(a0);
        if (rg + 3 < NR) buf2[r1 * DD + d] = collapse2(a1);
    }
    __syncthreads();
    // step 2: qpre[r][f] = SCALE * sum_d t[r][d] * Wk[d][f]
    {
        int f = tid & 255, rg = tid >> 8;
        int r0 = rg, r1 = (rg + 3 < NR) ? rg + 3 : r0;
        ull a0 = 0ull, a1 = 0ull;
        const ulonglong2* wk = (const ulonglong2*)g_Wkcp;
        for (int d4 = 0; d4 < DD / 4; d4++) {
            ulonglong2 ww = wk[d4 * DD + f];
            ulonglong2 t0 = *(const ulonglong2*)&buf2[r0 * DD + d4 * 4];
            ulonglong2 t1 = *(const ulonglong2*)&buf2[r1 * DD + d4 * 4];
            a0 = fma2(t0.x, ww.x, a0); a0 = fma2(t0.y, ww.y, a0);
            a1 = fma2(t1.x, ww.x, a1); a1 = fma2(t1.y, ww.y, a1);
        }
        float wt = lfw[f], bt = lfb[f];
        #pragma unroll
        for (int k = 0; k < 2; k++) {
            int r = (k == 0) ? r0 : r1;
            if (k == 1 && rg + 3 >= NR) break;
            float qpre = collapse2(k == 0 ? a0 : a1) * SCALEF;
            g_qt[(b * KK + rbase + r) * DD + f] = qpre * wt;
            float part = qpre * bt;
            #pragma unroll
            for (int o = 16; o; o >>= 1) part += __shfl_xor_sync(0xffffffffu, part, o);
            if (l == 0) atomicAdd(&sQB[r], part);
        }
    }
    __syncthreads();
    if (tid < NR) g_qbias[b * KK + rbase + tid] = sQB[tid];
}

// ------------------------- initial qgen (copies slots too) -------------------------
__global__ void __launch_bounds__(768) k_qgen0(
    const float* __restrict__ slots0,
    const float* __restrict__ lsw, const float* __restrict__ lsb,
    const float* __restrict__ lfw, const float* __restrict__ lfb)
{
    __shared__ __align__(16) float buf4[6 * DD];
    __shared__ __align__(16) float buf0[6 * DD];
    __shared__ __align__(16) float buf2[6 * DD];
    __shared__ float stat[32], sQB[16];
    int b = blockIdx.x, rh = blockIdx.y;
    int NR = (rh == 0) ? 6 : 5, rbase = rh * 6;
    int tid = threadIdx.x;
    for (int idx = tid; idx < NR * DD; idx += 768) {
        float v = slots0[(b * KK + rbase) * DD + idx];
        g_slots[(b * KK + rbase) * DD + idx] = v;
        buf4[idx] = v;
    }
    __syncthreads();
    qgen_core(b, rbase, NR, buf4, buf0, buf2, stat, sQB, lsw, lsb, lfw, lfb);
}

// ------------------------- per-iter: streaming attention (unchanged) -------------------------
__global__ void __launch_bounds__(128) k_attn() {
    __shared__ float sC[2][KK * DD];
    __shared__ float sS4[4][16];
    int b = blockIdx.x, sp = blockIdx.y;
    int tid = threadIdx.x, w = tid >> 5, l = tid & 31;

    ull q2[KK][4];
    {
        const float4* qp = (const float4*)(g_qt + (size_t)b * KK * DD);
        #pragma unroll
        for (int i = 0; i < KK; i++) {
            float4 a = qp[i * 64 + 2 * l], c = qp[i * 64 + 2 * l + 1];
            q2[i][0] = pk2(a.x, a.y); q2[i][1] = pk2(a.z, a.w);
            q2[i][2] = pk2(c.x, c.y); q2[i][3] = pk2(c.z, c.w);
        }
    }
    float qb_[KK];
    #pragma unroll
    for (int i = 0; i < KK; i++) qb_[i] = g_qbias[b * KK + i];

    ull U2[KK][4];
    float Sacc[KK];
    #pragma unroll
    for (int i = 0; i < KK; i++) {
        Sacc[i] = 0.f;
        #pragma unroll
        for (int k = 0; k < 4; k++) U2[i][k] = 0ull;
    }

    int j0 = sp * TOKB + w * TOKW;
    const float4* xrow = (const float4*)(g_xh + ((size_t)b * NN + j0) * DD);

    float4 xa = xrow[2 * l], xb = xrow[2 * l + 1];
    for (int tt = 0; tt < TOKW; tt++) {
        int nt = (tt + 1 < TOKW) ? tt + 1 : tt;
        float4 na = xrow[nt * 64 + 2 * l];
        float4 nb = xrow[nt * 64 + 2 * l + 1];

        ull n2[4];
        n2[0] = pk2(xa.x, xa.y); n2[1] = pk2(xa.z, xa.w);
        n2[2] = pk2(xb.x, xb.y); n2[3] = pk2(xb.z, xb.w);

        float p[KK];
        #pragma unroll
        for (int i = 0; i < KK; i++) {
            ull t2 = mul2(q2[i][3], n2[3]);
            t2 = fma2(q2[i][2], n2[2], t2);
            t2 = fma2(q2[i][1], n2[1], t2);
            t2 = fma2(q2[i][0], n2[0], t2);
            p[i] = collapse2(t2);
        }
        #pragma unroll
        for (int o = 16; o; o >>= 1) {
            #pragma unroll
            for (int i = 0; i < KK; i++) p[i] += __shfl_xor_sync(0xffffffffu, p[i], o);
        }
        float mx = p[0] + qb_[0];
        #pragma unroll
        for (int i = 0; i < KK; i++) { p[i] += qb_[i]; mx = fmaxf(mx, p[i]); }
        float se = 0.f;
        #pragma unroll
        for (int i = 0; i < KK; i++) { p[i] = __expf(p[i] - mx); se += p[i]; }
        float inv = 1.f / se;
        #pragma unroll
        for (int i = 0; i < KK; i++) {
            float a = fmaf(p[i], inv, EPSF);
            Sacc[i] += a;
            ull a2 = pk2(a, a);
            U2[i][0] = fma2(a2, n2[0], U2[i][0]);
            U2[i][1] = fma2(a2, n2[1], U2[i][1]);
            U2[i][2] = fma2(a2, n2[2], U2[i][2]);
            U2[i][3] = fma2(a2, n2[3], U2[i][3]);
        }
        xa = na; xb = nb;
    }

    float* myc = sC[w & 1];
    if (w < 2) {
        #pragma unroll
        for (int i = 0; i < KK; i++) {
            float u0,u1,u2,u3,u4,u5,u6,u7;
            upk2(u0,u1,U2[i][0]); upk2(u2,u3,U2[i][1]);
            upk2(u4,u5,U2[i][2]); upk2(u6,u7,U2[i][3]);
            *(float4*)&myc[i * DD + 8 * l]     = make_float4(u0,u1,u2,u3);
            *(float4*)&myc[i * DD + 8 * l + 4] = make_float4(u4,u5,u6,u7);
        }
    }
    __syncthreads();
    if (w >= 2) {
        #pragma unroll
        for (int i = 0; i < KK; i++) {
            float u0,u1,u2,u3,u4,u5,u6,u7;
            upk2(u0,u1,U2[i][0]); upk2(u2,u3,U2[i][1]);
            upk2(u4,u5,U2[i][2]); upk2(u6,u7,U2[i][3]);
            float4 a = *(float4*)&myc[i * DD + 8 * l];
            float4 c = *(float4*)&myc[i * DD + 8 * l + 4];
            a.x += u0; a.y += u1; a.z += u2; a.w += u3;
            c.x += u4; c.y += u5; c.z += u6; c.w += u7;
            *(float4*)&myc[i * DD + 8 * l]     = a;
            *(float4*)&myc[i * DD + 8 * l + 4] = c;
        }
    }
    if (l == 0) {
        #pragma unroll
        for (int i = 0; i < KK; i++) sS4[w][i] = Sacc[i];
    }
    __syncthreads();
    float* outp = g_pU + ((size_t)(b * SPLITN + sp)) * (KK * DD);
    for (int idx = tid; idx < KK * DD; idx += 128)
        outp[idx] = sC[0][idx] + sC[1][idx];
    if (tid < KK)
        g_pS[(b * SPLITN + sp) * 16 + tid] =
            sS4[0][tid] + sS4[1][tid] + sS4[2][tid] + sS4[3][tid];
}

// ------------------------- per-iter: fused update, split by slot-halves -------------------------
__global__ void __launch_bounds__(768) k_update(
    const float* __restrict__ lfw, const float* __restrict__ lfb,
    const float* __restrict__ lpw, const float* __restrict__ lpb,
    const float* __restrict__ lsw, const float* __restrict__ lsb,
    const float* __restrict__ bih, const float* __restrict__ bhh,
    const float* __restrict__ b1,  const float* __restrict__ b2,
    float* __restrict__ outp)
{
    __shared__ __align__(16) float buf0[6 * DD];    // un / LN_p / LN_s
    __shared__ __align__(16) float buf1[6 * DD];    // prev slots -> hy
    __shared__ __align__(16) float buf2[6 * 768];   // gates -> h1 -> t
    __shared__ __align__(16) float buf3[6 * DD];    // h_n
    __shared__ __align__(16) float buf4[6 * DD];    // updates -> new slots
    __shared__ float sS[16], stat[32], sQB[16];

    int b = blockIdx.x, rh = blockIdx.y;
    int NR = (rh == 0) ? 6 : 5, rbase = rh * 6;
    int tid = threadIdx.x, w = tid >> 5, l = tid & 31;

    // ---- Stage A: combine attention partials + load prev slots ----
    if (tid < NR) {
        float s = 0.f;
        #pragma unroll
        for (int sp = 0; sp < SPLITN; sp++) s += g_pS[(b * SPLITN + sp) * 16 + rbase + tid];
        sS[tid] = s;
    }
    for (int idx = tid; idx < NR * DD; idx += 768) {
        float u = 0.f;
        #pragma unroll
        for (int sp = 0; sp < SPLITN; sp++)
            u += g_pU[((size_t)(b * SPLITN + sp)) * (KK * DD) + rbase * DD + idx];
        buf0[idx] = u;
        buf1[idx] = g_slots[(b * KK + rbase) * DD + idx];
    }
    __syncthreads();
    for (int idx = tid; idx < NR * DD; idx += 768) {
        int r = idx >> 8, d = idx & 255;
        buf0[idx] = fmaf(lfw[d], buf0[idx] / sS[r], lfb[d]);
    }
    __syncthreads();

    // ---- Stage B: updates[r][d] = sum_e un[r][e] * Wv[d][e] ----
    {
        int d = tid & 255, rg = tid >> 8;
        int r0 = rg, r1 = (rg + 3 < NR) ? rg + 3 : r0;
        ull a0 = 0ull, a1 = 0ull;
        const ulonglong2* wv = (const ulonglong2*)g_Wvp;
        for (int e4 = 0; e4 < DD / 4; e4++) {
            ulonglong2 ww = wv[e4 * DD + d];
            ulonglong2 u0 = *(const ulonglong2*)&buf0[r0 * DD + e4 * 4];
            ulonglong2 u1 = *(const ulonglong2*)&buf0[r1 * DD + e4 * 4];
            a0 = fma2(u0.x, ww.x, a0); a0 = fma2(u0.y, ww.y, a0);
            a1 = fma2(u1.x, ww.x, a1); a1 = fma2(u1.y, ww.y, a1);
        }
        buf4[r0 * DD + d] = collapse2(a0);
        if (rg + 3 < NR) buf4[r1 * DD + d] = collapse2(a1);
    }
    __syncthreads();

    // ---- Stage C: GRU gates, thread j owns gate-row j (coalesced packed weights) ----
    {
        int j = tid;
        ull gi2[6], gh2[6];
        #pragma unroll
        for (int r = 0; r < 6; r++) { gi2[r] = 0ull; gh2[r] = 0ull; }
        const ulonglong2* wi = (const ulonglong2*)g_Wihp;
        const ulonglong2* wh = (const ulonglong2*)g_Whhp;
        for (int e4 = 0; e4 < DD / 4; e4++) {
            ulonglong2 a = wi[e4 * 768 + j];
            ulonglong2 c = wh[e4 * 768 + j];
            #pragma unroll
            for (int r = 0; r < 6; r++) {
                int rr = (r < NR) ? r : NR - 1;
                ulonglong2 uu = *(const ulonglong2*)&buf4[rr * DD + e4 * 4];
                ulonglong2 hh = *(const ulonglong2*)&buf1[rr * DD + e4 * 4];
                gi2[r] = fma2(uu.x, a.x, gi2[r]);
                gi2[r] = fma2(uu.y, a.y, gi2[r]);
                gh2[r] = fma2(hh.x, c.x, gh2[r]);
                gh2[r] = fma2(hh.y, c.y, gh2[r]);
            }
        }
        float bi = bih[j], bh = bhh[j];
        if (j < 2 * DD) {
            #pragma unroll
            for (int r = 0; r < 6; r++)
                if (r < NR)
                    buf2[r * 768 + j] = (collapse2(gi2[r]) + bi) + (collapse2(gh2[r]) + bh);
        } else {
            #pragma unroll
            for (int r = 0; r < 6; r++)
                if (r < NR) {
                    buf2[r * 768 + j] = collapse2(gi2[r]) + bi;          // i_n
                    buf3[r * DD + (j - 2 * DD)] = collapse2(gh2[r]) + bh; // h_n
                }
        }
    }
    __syncthreads();

    // ---- Stage D: GRU nonlinearity ----
    if (tid < DD) {
        int d = tid;
        for (int r = 0; r < NR; r++) {
            float rg = sigm(buf2[r * 768 + d]);
            float zz = sigm(buf2[r * 768 + DD + d]);
            float nn = tanhf(fmaf(rg, buf3[r * DD + d], buf2[r * 768 + 2 * DD + d]));
            float hp = buf1[r * DD + d];
            buf1[r * DD + d] = fmaf(zz, hp - nn, nn);
        }
    }
    __syncthreads();
    // LN_p stats (warp per slot)
    if (w < NR) {
        float4 a = *(float4*)&buf1[w * DD + l * 8];
        float4 c = *(float4*)&buf1[w * DD + l * 8 + 4];
        float s = a.x + a.y + a.z + a.w + c.x + c.y + c.z + c.w;
        float q = a.x*a.x + a.y*a.y + a.z*a.z + a.w*a.w
                + c.x*c.x + c.y*c.y + c.z*c.z + c.w*c.w;
        #pragma unroll
        for (int o = 16; o; o >>= 1) {
            s += __shfl_xor_sync(0xffffffffu, s, o);
            q += __shfl_xor_sync(0xffffffffu, q, o);
        }
        if (l == 0) {
            float m = s * (1.f / DD);
            float var = fmaxf(q * (1.f / DD) - m * m, 0.f);
            stat[w] = m;
            stat[16 + w] = rsqrtf(var + LN_EPSF);
        }
    }
    __syncthreads();
    for (int idx = tid; idx < NR * DD; idx += 768) {
        int r = idx >> 8, d = idx & 255;
        buf0[idx] = fmaf((buf1[idx] - stat[r]) * stat[16 + r], lpw[d], lpb[d]);
    }
    __syncthreads();

    // ---- Stage E: MLP1 ----
    if (tid < HH) {
        int h = tid;
        ull a2[6];
        #pragma unroll
        for (int r = 0; r < 6; r++) a2[r] = 0ull;
        const ulonglong2* w1 = (const ulonglong2*)g_W1p;
        for (int e4 = 0; e4 < DD / 4; e4++) {
            ulonglong2 ww = w1[e4 * HH + h];
            #pragma unroll
            for (int r = 0; r < 6; r++) {
                int rr = (r < NR) ? r : NR - 1;
                ulonglong2 pp = *(const ulonglong2*)&buf0[rr * DD + e4 * 4];
                a2[r] = fma2(pp.x, ww.x, a2[r]);
                a2[r] = fma2(pp.y, ww.y, a2[r]);
            }
        }
        float bb = b1[h];
        __syncthreads();   // gates in buf2 fully consumed (stage D)
        #pragma unroll
        for (int r = 0; r < 6; r++)
            if (r < NR) buf2[r * HH + h] = fmaxf(collapse2(a2[r]) + bb, 0.f);
    } else {
        __syncthreads();
    }
    __syncthreads();

    // ---- Stage F: MLP2 + residual ----
    {
        int d = tid & 255, rg = tid >> 8;
        int r0 = rg, r1 = (rg + 3 < NR) ? rg + 3 : r0;
        ull a0 = 0ull, a1 = 0ull;
        const ulonglong2* w2 = (const ulonglong2*)g_W2p;
        for (int h4 = 0; h4 < HH / 4; h4++) {
            ulonglong2 ww = w2[h4 * DD + d];
            ulonglong2 h0 = *(const ulonglong2*)&buf2[r0 * HH + h4 * 4];
            ulonglong2 h1 = *(const ulonglong2*)&buf2[r1 * HH + h4 * 4];
            a0 = fma2(h0.x, ww.x, a0); a0 = fma2(h0.y, ww.y, a0);
            a1 = fma2(h1.x, ww.x, a1); a1 = fma2(h1.y, ww.y, a1);
        }
        float bb = b2[d];
        {
            float fin = collapse2(a0) + bb + buf1[r0 * DD + d];
            g_slots[(b * KK + rbase + r0) * DD + d] = fin;
            outp[(b * KK + rbase + r0) * DD + d] = fin;
            buf4[r0 * DD + d] = fin;
        }
        if (rg + 3 < NR) {
            float fin = collapse2(a1) + bb + buf1[r1 * DD + d];
            g_slots[(b * KK + rbase + r1) * DD + d] = fin;
            outp[(b * KK + rbase + r1) * DD + d] = fin;
            buf4[r1 * DD + d] = fin;
        }
    }
    __syncthreads();

    // ---- Stage G: qgen for next iteration ----
    qgen_core(b, rbase, NR, buf4, buf0, buf2, stat, sQB, lsw, lsb, lfw, lfb);
}

// ------------------------- launch -------------------------
extern "C" void kernel_launch(void* const* d_in, const int* in_sizes, int n_in,
                              void* d_out, int out_size) {
    const float* inputs = (const float*)d_in[0];
    const float* slots0 = (const float*)d_in[1];
    const float* ln_f_w = (const float*)d_in[2];
    const float* ln_f_b = (const float*)d_in[3];
    const float* ln_s_w = (const float*)d_in[4];
    const float* ln_s_b = (const float*)d_in[5];
    const float* ln_p_w = (const float*)d_in[6];
    const float* ln_p_b = (const float*)d_in[7];
    const float* Wq  = (const float*)d_in[8];
    const float* Wk  = (const float*)d_in[9];
    const float* Wv  = (const float*)d_in[10];
    const float* Wih = (const float*)d_in[11];
    const float* bih = (const float*)d_in[12];
    const float* Whh = (const float*)d_in[13];
    const float* bhh = (const float*)d_in[14];
    const float* W1  = (const float*)d_in[15];
    const float* b1  = (const float*)d_in[16];
    const float* W2  = (const float*)d_in[17];
    const float* b2  = (const float*)d_in[18];
    float* outp = (float*)d_out;

    // launch order: 0 prep, 1 qgen0, 2 attn, 3 update, 4 attn, ... (ncu -s5 -> k_update)
    k_prep<<<XHB + 832, 256>>>(inputs, Wq, Wk, Wv, Wih, Whh, W1, W2);
    k_qgen0<<<dim3(BB, 2), 768>>>(slots0, ln_s_w, ln_s_b, ln_f_w, ln_f_b);

    for (int it = 0; it < NITER; it++) {
        k_attn<<<dim3(BB, SPLITN), 128>>>();
        k_update<<<dim3(BB, 2), 768>>>(
            ln_f_w, ln_f_b, ln_p_w, ln_p_b, ln_s_w, ln_s_b,
            bih, bhh, b1, b2, outp);
    }
}